// round 2
// baseline (speedup 1.0000x reference)
#include <cuda_runtime.h>
#include <cstdint>

#define NN 100000
#define EE 1600000
#define GG 1000
#define IN_C 32
#define EDGE_C 16
#define DESCC 200
#define HH 64
#define LL 3
#define SCAN_BLOCKS 98   // ceil(NN/1024)

// ---------------- device scratch ----------------
__device__ float g_h[NN * HH];
__device__ float g_hp[NN * HH];
__device__ float g_agg[NN * HH];
__device__ float g_cnt[NN];
__device__ int   g_icnt[NN];
__device__ int   g_rowtmp[NN];
__device__ int   g_rowptr[NN + 1];
__device__ int   g_cursor[NN];
__device__ int   g_blocksum[128];
__device__ int   g_blockoff[128];
__device__ int   g_srcp[EE];
__device__ float g_eaperm[EE * EDGE_C];     // 102.4 MB, CSR-ordered edge_attr
__device__ float g_Wcomb[LL * EDGE_C * HH];
__device__ float g_bcomb[LL * HH];
__device__ float g_pool[GG * HH];
__device__ float g_pcnt[GG];
__device__ int g_ei64;
__device__ int g_b64;

// ---------------- f32x2 helpers ----------------
__device__ __forceinline__ unsigned long long pack2(float lo, float hi) {
    unsigned long long r;
    asm("mov.b64 %0, {%1, %2};" : "=l"(r) : "f"(lo), "f"(hi));
    return r;
}
__device__ __forceinline__ void unpack2(unsigned long long v, float& lo, float& hi) {
    asm("mov.b64 {%0, %1}, %2;" : "=f"(lo), "=f"(hi) : "l"(v));
}
__device__ __forceinline__ unsigned long long fma2(unsigned long long a,
                                                   unsigned long long b,
                                                   unsigned long long c) {
    unsigned long long d;
    asm("fma.rn.f32x2 %0, %1, %2, %3;" : "=l"(d) : "l"(a), "l"(b), "l"(c));
    return d;
}
__device__ __forceinline__ unsigned long long add2(unsigned long long a,
                                                   unsigned long long b) {
    unsigned long long d;
    asm("add.rn.f32x2 %0, %1, %2;" : "=l"(d) : "l"(a), "l"(b));
    return d;
}

// ---------------- dtype detection ----------------
__global__ void detect_kernel(const void* ei, const void* batch) {
    if (threadIdx.x == 0) {
        const long long* p = (const long long*)ei;
        int ok = 1;
        for (int i = 1; i <= 16; i++) {
            long long v = p[EE - i];
            if (v < 0 || v >= NN) ok = 0;
        }
        g_ei64 = ok;
        const long long* q = (const long long*)batch;
        int okb = 1;
        for (int i = 1; i <= 16; i++) {
            long long v = q[NN / 2 - i];
            if (v < 0 || v >= GG) okb = 0;
        }
        g_b64 = okb;
    }
}

__device__ __forceinline__ long long load_idx(const void* p, long long i, int is64) {
    return is64 ? ((const long long*)p)[i] : (long long)((const int*)p)[i];
}

// ---------------- zero ----------------
__global__ void zero_misc_kernel() {
    int i = blockIdx.x * blockDim.x + threadIdx.x;
    int stride = gridDim.x * blockDim.x;
    for (int k = i; k < NN; k += stride) g_icnt[k] = 0;
    for (int k = i; k < GG * HH; k += stride) g_pool[k] = 0.f;
    for (int k = i; k < GG; k += stride) g_pcnt[k] = 0.f;
}

// ---------------- in-degree histogram ----------------
__global__ void count_kernel(const void* ei) {
    int is64 = g_ei64;
    int i = blockIdx.x * blockDim.x + threadIdx.x;
    int stride = gridDim.x * blockDim.x;
    for (; i < EE; i += stride) {
        long long dst = load_idx(ei, (long long)EE + i, is64);
        atomicAdd(&g_icnt[(int)dst], 1);
    }
}

// ---------------- 3-phase exclusive scan ----------------
__global__ void scan1_kernel() {
    __shared__ int s[1024];
    int i = blockIdx.x * 1024 + threadIdx.x;
    int v = (i < NN) ? g_icnt[i] : 0;
    s[threadIdx.x] = v;
    __syncthreads();
    for (int off = 1; off < 1024; off <<= 1) {
        int t = (threadIdx.x >= off) ? s[threadIdx.x - off] : 0;
        __syncthreads();
        s[threadIdx.x] += t;
        __syncthreads();
    }
    if (i < NN) g_rowtmp[i] = s[threadIdx.x] - v;
    if (threadIdx.x == 1023) g_blocksum[blockIdx.x] = s[1023];
}
__global__ void scan2_kernel() {
    __shared__ int s[128];
    int v = (threadIdx.x < SCAN_BLOCKS) ? g_blocksum[threadIdx.x] : 0;
    s[threadIdx.x] = v;
    __syncthreads();
    for (int off = 1; off < 128; off <<= 1) {
        int t = (threadIdx.x >= off) ? s[threadIdx.x - off] : 0;
        __syncthreads();
        s[threadIdx.x] += t;
        __syncthreads();
    }
    g_blockoff[threadIdx.x] = s[threadIdx.x] - v;
}
__global__ void scan3_kernel() {
    int i = blockIdx.x * 1024 + threadIdx.x;
    if (i < NN) {
        int r = g_rowtmp[i] + g_blockoff[blockIdx.x];
        g_rowptr[i] = r;
        g_cursor[i] = r;
        g_cnt[i] = (float)g_icnt[i];
    }
    if (i == 0) g_rowptr[NN] = EE;
}

// ---------------- CSR scatter: permute src + edge_attr into dst-grouped order ----------------
__global__ void scatter_kernel(const void* __restrict__ ei,
                               const float* __restrict__ edge_attr) {
    int is64 = g_ei64;
    int i = blockIdx.x * blockDim.x + threadIdx.x;
    int stride = gridDim.x * blockDim.x;
    for (; i < EE; i += stride) {
        int src = (int)load_idx(ei, i, is64);
        int dst = (int)load_idx(ei, (long long)EE + i, is64);
        int pos = atomicAdd(&g_cursor[dst], 1);
        g_srcp[pos] = src;
        const float4* s = (const float4*)(edge_attr + (long long)i * EDGE_C);
        float4* d = (float4*)(g_eaperm + (long long)pos * EDGE_C);
        d[0] = s[0]; d[1] = s[1]; d[2] = s[2]; d[3] = s[3];
    }
}

// ---------------- composed edge weights ----------------
__global__ void wcomb_kernel(const float* __restrict__ edge_W,
                             const float* __restrict__ edge_b,
                             const float* __restrict__ emW1,
                             const float* __restrict__ emb1) {
    __shared__ float sW1[HH * HH];
    __shared__ float sEW[EDGE_C * HH];
    int l = blockIdx.x;
    int tid = threadIdx.x; // 1024
    const float* W1l = emW1 + l * (2 * HH * HH) + HH * HH; // lower rows (64..127)
    for (int i = tid; i < HH * HH; i += 1024) sW1[i] = W1l[i];
    if (tid < EDGE_C * HH) sEW[tid] = edge_W[tid];
    __syncthreads();
    int k = tid >> 6, j = tid & 63;
    float acc = 0.f;
#pragma unroll 16
    for (int t = 0; t < HH; t++) acc += sEW[k * HH + t] * sW1[t * HH + j];
    g_Wcomb[l * EDGE_C * HH + k * HH + j] = acc;
    if (k == 0) {
        float accb = emb1[l * HH + j];
        for (int t = 0; t < HH; t++) accb += edge_b[t] * sW1[t * HH + j];
        g_bcomb[l * HH + j] = accb;
    }
}

// ---------------- node init ----------------
__global__ void init_node_kernel(const float* __restrict__ x,
                                 const float* __restrict__ nW,
                                 const float* __restrict__ nb,
                                 const float* __restrict__ emW1) {
    __shared__ float sW[IN_C * HH];
    __shared__ float sP[HH * HH];
    __shared__ float sb[HH];
    __shared__ float sx[4][IN_C];
    __shared__ float sh[4][HH];
    int tid = threadIdx.x; // 256
    for (int i = tid; i < IN_C * HH; i += 256) sW[i] = nW[i];
    for (int i = tid; i < HH * HH; i += 256) sP[i] = emW1[i]; // layer0 upper rows
    if (tid < HH) sb[tid] = nb[tid];
    int tx = tid & 63, ty = tid >> 6;
    int node = blockIdx.x * 4 + ty;
    __syncthreads();
    if (node < NN && tx < IN_C) sx[ty][tx] = x[node * IN_C + tx];
    __syncthreads();
    float h = 0.f;
    if (node < NN) {
        h = sb[tx];
#pragma unroll
        for (int k = 0; k < IN_C; k++) h += sx[ty][k] * sW[k * HH + tx];
        g_h[node * HH + tx] = h;
        sh[ty][tx] = h;
    }
    __syncthreads();
    if (node < NN) {
        float hp = 0.f;
#pragma unroll 16
        for (int k = 0; k < HH; k++) hp += sh[ty][k] * sP[k * HH + tx];
        g_hp[node * HH + tx] = hp;
    }
}

// ---------------- edge kernel (CSR, warp-per-node, register accumulation) ----------------
// agg[v] = sum over in-edges e of relu(hp[src(e)] + ea_perm[e]@Wcomb[l] + bcomb[l])
__global__ __launch_bounds__(256) void edge_csr_kernel(int l) {
    const int lane = threadIdx.x & 31;
    const int node = blockIdx.x * 8 + (threadIdx.x >> 5);  // 12500 * 8 = NN exactly
    const float* Wc = g_Wcomb + l * EDGE_C * HH;
    // weights into registers: wk[k] = {W[k][2*lane], W[k][2*lane+1]}
    unsigned long long wk[EDGE_C];
#pragma unroll
    for (int k = 0; k < EDGE_C; k++)
        wk[k] = *(const unsigned long long*)(Wc + k * HH + 2 * lane);
    unsigned long long bias2 = *(const unsigned long long*)(g_bcomb + l * HH + 2 * lane);
    int base = g_rowptr[node];
    int deg = g_rowptr[node + 1] - base;
    unsigned long long acc = 0ull; // {0.f, 0.f} bit pattern
    for (int j = 0; j < deg; j++) {
        int eidx = base + j;
        int src = g_srcp[eidx];                           // uniform across warp
        float ea = g_eaperm[(long long)eidx * EDGE_C + (lane & 15)];
        unsigned long long h0 = *(const unsigned long long*)(g_hp + src * HH + 2 * lane);
        h0 = add2(h0, bias2);
        unsigned long long h1 = 0ull;
#pragma unroll
        for (int k = 0; k < EDGE_C; k += 2) {
            float a0 = __shfl_sync(0xffffffffu, ea, k);
            float a1 = __shfl_sync(0xffffffffu, ea, k + 1);
            h0 = fma2(pack2(a0, a0), wk[k], h0);
            h1 = fma2(pack2(a1, a1), wk[k + 1], h1);
        }
        unsigned long long hsum = add2(h0, h1);
        float lo, hi;
        unpack2(hsum, lo, hi);
        lo = fmaxf(lo, 0.f);
        hi = fmaxf(hi, 0.f);
        acc = add2(acc, pack2(lo, hi));
    }
    *(unsigned long long*)(g_agg + node * HH + 2 * lane) = acc;
}

// ---------------- fused node update (unchanged from R1) ----------------
#define NPT 16
#define NU_SMEM_FLOATS (4096 + 8192 + 4096 + 4096 + 3 * 64 + NPT * 64 + NPT * 128 + NPT * 64 + NPT)
__global__ void node_update_kernel(const float* __restrict__ emW2, const float* __restrict__ emb2,
                                   const float* __restrict__ umW1, const float* __restrict__ umb1,
                                   const float* __restrict__ umW2, const float* __restrict__ umb2,
                                   const float* __restrict__ emW1, int l, int has_next) {
    extern __shared__ float sm[];
    float* sW2 = sm;
    float* sU1 = sW2 + 4096;
    float* sU2 = sU1 + 8192;
    float* sP  = sU2 + 4096;
    float* sb2 = sP + 4096;
    float* sub1 = sb2 + 64;
    float* sub2 = sub1 + 64;
    float* sA = sub2 + 64;
    float* sU = sA + NPT * 64;
    float* sT = sU + NPT * 128;
    float* sC = sT + NPT * 64;
    int tid = threadIdx.x; // 256
    const float* w2 = emW2 + l * 4096;
    const float* u1 = umW1 + l * 8192;
    const float* u2 = umW2 + l * 4096;
    const float* pn = emW1 + (l + 1) * 8192;
    for (int i = tid; i < 4096; i += 256) {
        sW2[i] = w2[i]; sU2[i] = u2[i]; sP[i] = has_next ? pn[i] : 0.f;
    }
    for (int i = tid; i < 8192; i += 256) sU1[i] = u1[i];
    if (tid < 64) { sb2[tid] = emb2[l * 64 + tid]; sub1[tid] = umb1[l * 64 + tid]; sub2[tid] = umb2[l * 64 + tid]; }
    __syncthreads();
    int tx = tid & 63, g = tid >> 6;
    int n0 = g * 4, n1 = g * 4 + 1, n2 = g * 4 + 2, n3 = g * 4 + 3;
    for (int nb = blockIdx.x * NPT; nb < NN; nb += gridDim.x * NPT) {
#pragma unroll
        for (int r = 0; r < NPT * 64 / 256; r++) {
            int idx = tid + r * 256;
            int nloc = idx >> 6, ch = idx & 63;
            int node = nb + nloc;
            float a = 0.f, hv = 0.f;
            if (node < NN) { a = g_agg[(long long)node * 64 + ch]; hv = g_h[(long long)node * 64 + ch]; }
            sA[nloc * 64 + ch] = a;
            sU[nloc * 128 + ch] = hv;
        }
        if (tid < NPT) { int node = nb + tid; sC[tid] = node < NN ? g_cnt[node] : 0.f; }
        __syncthreads();
        {
            float a0 = sC[n0] * sb2[tx], a1 = sC[n1] * sb2[tx], a2 = sC[n2] * sb2[tx], a3 = sC[n3] * sb2[tx];
#pragma unroll 16
            for (int k = 0; k < 64; k++) {
                float w = sW2[k * 64 + tx];
                a0 += sA[n0 * 64 + k] * w; a1 += sA[n1 * 64 + k] * w;
                a2 += sA[n2 * 64 + k] * w; a3 += sA[n3 * 64 + k] * w;
            }
            sU[n0 * 128 + 64 + tx] = a0; sU[n1 * 128 + 64 + tx] = a1;
            sU[n2 * 128 + 64 + tx] = a2; sU[n3 * 128 + 64 + tx] = a3;
        }
        __syncthreads();
        {
            float a0 = sub1[tx], a1 = a0, a2 = a0, a3 = a0;
#pragma unroll 16
            for (int k = 0; k < 128; k++) {
                float w = sU1[k * 64 + tx];
                a0 += sU[n0 * 128 + k] * w; a1 += sU[n1 * 128 + k] * w;
                a2 += sU[n2 * 128 + k] * w; a3 += sU[n3 * 128 + k] * w;
            }
            sT[n0 * 64 + tx] = fmaxf(a0, 0.f); sT[n1 * 64 + tx] = fmaxf(a1, 0.f);
            sT[n2 * 64 + tx] = fmaxf(a2, 0.f); sT[n3 * 64 + tx] = fmaxf(a3, 0.f);
        }
        __syncthreads();
        {
            float a0 = sub2[tx], a1 = a0, a2 = a0, a3 = a0;
#pragma unroll 16
            for (int k = 0; k < 64; k++) {
                float w = sU2[k * 64 + tx];
                a0 += sT[n0 * 64 + k] * w; a1 += sT[n1 * 64 + k] * w;
                a2 += sT[n2 * 64 + k] * w; a3 += sT[n3 * 64 + k] * w;
            }
            if (nb + n0 < NN) g_h[(long long)(nb + n0) * 64 + tx] = a0;
            if (nb + n1 < NN) g_h[(long long)(nb + n1) * 64 + tx] = a1;
            if (nb + n2 < NN) g_h[(long long)(nb + n2) * 64 + tx] = a2;
            if (nb + n3 < NN) g_h[(long long)(nb + n3) * 64 + tx] = a3;
            __syncthreads();
            sA[n0 * 64 + tx] = a0; sA[n1 * 64 + tx] = a1;
            sA[n2 * 64 + tx] = a2; sA[n3 * 64 + tx] = a3;
        }
        __syncthreads();
        if (has_next) {
            float a0 = 0.f, a1 = 0.f, a2 = 0.f, a3 = 0.f;
#pragma unroll 16
            for (int k = 0; k < 64; k++) {
                float w = sP[k * 64 + tx];
                a0 += sA[n0 * 64 + k] * w; a1 += sA[n1 * 64 + k] * w;
                a2 += sA[n2 * 64 + k] * w; a3 += sA[n3 * 64 + k] * w;
            }
            if (nb + n0 < NN) g_hp[(long long)(nb + n0) * 64 + tx] = a0;
            if (nb + n1 < NN) g_hp[(long long)(nb + n1) * 64 + tx] = a1;
            if (nb + n2 < NN) g_hp[(long long)(nb + n2) * 64 + tx] = a2;
            if (nb + n3 < NN) g_hp[(long long)(nb + n3) * 64 + tx] = a3;
        }
        __syncthreads();
    }
}

// ---------------- global mean pool ----------------
__global__ void pool_kernel(const void* __restrict__ batch) {
    int is64 = g_b64;
    long long i = (long long)blockIdx.x * blockDim.x + threadIdx.x;
    if (i >= (long long)NN * 64) return;
    long long node = i >> 6; int ch = (int)(i & 63);
    long long b = load_idx(batch, node, is64);
    atomicAdd(&g_pool[b * 64 + ch], g_h[i]);
    if (ch == 0) atomicAdd(&g_pcnt[b], 1.0f);
}

// ---------------- readout ----------------
__global__ void readout_kernel(const float* __restrict__ desc,
                               const float* __restrict__ W1, const float* __restrict__ b1,
                               const float* __restrict__ W2, const float* __restrict__ b2,
                               float* __restrict__ out) {
    __shared__ float r[HH + DESCC];
    __shared__ float st[128];
    int g = blockIdx.x, tid = threadIdx.x; // 128 threads
    float cn = fmaxf(g_pcnt[g], 1.0f);
    for (int i = tid; i < HH; i += 128) r[i] = g_pool[g * HH + i] / cn;
    for (int i = tid; i < DESCC; i += 128) r[HH + i] = desc[(long long)g * DESCC + i];
    __syncthreads();
    float acc = b1[tid];
#pragma unroll 8
    for (int k = 0; k < HH + DESCC; k++) acc += r[k] * W1[k * 128 + tid];
    acc = fmaxf(acc, 0.f);
    st[tid] = acc * W2[tid];
    __syncthreads();
    for (int s = 64; s > 0; s >>= 1) {
        if (tid < s) st[tid] += st[tid + s];
        __syncthreads();
    }
    if (tid == 0) out[g] = 1.0f / (1.0f + expf(-(st[0] + b2[0])));
}

// ---------------- launch ----------------
extern "C" void kernel_launch(void* const* d_in, const int* in_sizes, int n_in,
                              void* d_out, int out_size) {
    const float* x       = (const float*)d_in[0];
    const void*  ei      = d_in[1];
    const float* eattr   = (const float*)d_in[2];
    const void*  batch   = d_in[3];
    const float* desc    = (const float*)d_in[4];
    const float* node_W  = (const float*)d_in[5];
    const float* node_b  = (const float*)d_in[6];
    const float* edge_W  = (const float*)d_in[7];
    const float* edge_b  = (const float*)d_in[8];
    const float* emW1    = (const float*)d_in[9];
    const float* emb1    = (const float*)d_in[10];
    const float* emW2    = (const float*)d_in[11];
    const float* emb2    = (const float*)d_in[12];
    const float* umW1    = (const float*)d_in[13];
    const float* umb1    = (const float*)d_in[14];
    const float* umW2    = (const float*)d_in[15];
    const float* umb2    = (const float*)d_in[16];
    const float* roW1    = (const float*)d_in[17];
    const float* rob1    = (const float*)d_in[18];
    const float* roW2    = (const float*)d_in[19];
    const float* rob2    = (const float*)d_in[20];
    float* out = (float*)d_out;

    const int nu_smem = NU_SMEM_FLOATS * (int)sizeof(float);
    cudaFuncSetAttribute(node_update_kernel,
                         cudaFuncAttributeMaxDynamicSharedMemorySize, nu_smem);

    detect_kernel<<<1, 32>>>(ei, batch);
    zero_misc_kernel<<<512, 256>>>();
    count_kernel<<<2048, 256>>>(ei);
    scan1_kernel<<<SCAN_BLOCKS, 1024>>>();
    scan2_kernel<<<1, 128>>>();
    scan3_kernel<<<SCAN_BLOCKS, 1024>>>();
    scatter_kernel<<<2048, 256>>>(ei, eattr);
    wcomb_kernel<<<LL, 1024>>>(edge_W, edge_b, emW1, emb1);
    init_node_kernel<<<(NN + 3) / 4, 256>>>(x, node_W, node_b, emW1);
    for (int l = 0; l < LL; l++) {
        edge_csr_kernel<<<NN / 8, 256>>>(l);
        node_update_kernel<<<296, 256, nu_smem>>>(emW2, emb2, umW1, umb1,
                                                  umW2, umb2, emW1, l, l < LL - 1 ? 1 : 0);
    }
    pool_kernel<<<(NN * 64 + 255) / 256, 256>>>(batch);
    readout_kernel<<<GG, 128>>>(desc, roW1, rob1, roW2, rob2, out);
}

// round 3
// speedup vs baseline: 1.2097x; 1.2097x over previous
#include <cuda_runtime.h>
#include <cstdint>

#define NN 100000
#define EE 1600000
#define GG 1000
#define IN_C 32
#define EDGE_C 16
#define DESCC 200
#define HH 64
#define LL 3

typedef unsigned long long ull;

// ---------------- device scratch ----------------
__device__ float g_h[NN * HH];
__device__ float g_hp[NN * HH];
__device__ float g_agg[NN * HH];
__device__ float g_cnt[NN];
__device__ float g_Wcomb[LL * EDGE_C * HH];
__device__ float g_bcomb[LL * HH];
__device__ float g_V1[LL * 2 * HH * HH];   // [umW1_top ; emW2@umW1_bot]
__device__ float g_bae[LL * HH];           // emb2 @ umW1_bot
__device__ float g_Whp[LL * HH * HH];      // umW2 @ emW1[l+1]_top
__device__ float g_bhp[LL * HH];           // umb2 @ emW1[l+1]_top
__device__ float g_pool[GG * HH];
__device__ float g_pcnt[GG];
__device__ int g_ei64;
__device__ int g_b64;

// ---------------- f32x2 helpers ----------------
__device__ __forceinline__ ull pack2(float lo, float hi) {
    ull r;
    asm("mov.b64 %0, {%1, %2};" : "=l"(r) : "f"(lo), "f"(hi));
    return r;
}
__device__ __forceinline__ void unpack2(ull v, float& lo, float& hi) {
    asm("mov.b64 {%0, %1}, %2;" : "=f"(lo), "=f"(hi) : "l"(v));
}
__device__ __forceinline__ ull fma2(ull a, ull b, ull c) {
    ull d;
    asm("fma.rn.f32x2 %0, %1, %2, %3;" : "=l"(d) : "l"(a), "l"(b), "l"(c));
    return d;
}

// ---------------- dtype detection ----------------
__global__ void detect_kernel(const void* ei, const void* batch) {
    if (threadIdx.x == 0) {
        const long long* p = (const long long*)ei;
        int ok = 1;
        for (int i = 1; i <= 16; i++) {
            long long v = p[EE - i];
            if (v < 0 || v >= NN) ok = 0;
        }
        g_ei64 = ok;
        const long long* q = (const long long*)batch;
        int okb = 1;
        for (int i = 1; i <= 16; i++) {
            long long v = q[NN / 2 - i];
            if (v < 0 || v >= GG) okb = 0;
        }
        g_b64 = okb;
    }
}

__device__ __forceinline__ long long load_idx(const void* p, long long i, int is64) {
    return is64 ? ((const long long*)p)[i] : (long long)((const int*)p)[i];
}

// ---------------- zero kernels ----------------
__global__ void zero_agg_kernel() {
    int i = blockIdx.x * blockDim.x + threadIdx.x;
    int stride = gridDim.x * blockDim.x;
    float4* p = (float4*)g_agg;
    const int n4 = NN * HH / 4;
    float4 z = make_float4(0.f, 0.f, 0.f, 0.f);
    for (; i < n4; i += stride) p[i] = z;
}

__global__ void zero_misc_kernel() {
    int i = blockIdx.x * blockDim.x + threadIdx.x;
    int stride = gridDim.x * blockDim.x;
    for (int k = i; k < NN; k += stride) g_cnt[k] = 0.f;
    for (int k = i; k < GG * HH; k += stride) g_pool[k] = 0.f;
    for (int k = i; k < GG; k += stride) g_pcnt[k] = 0.f;
}

// ---------------- in-degree ----------------
__global__ void count_kernel(const void* ei) {
    int is64 = g_ei64;
    int i = blockIdx.x * blockDim.x + threadIdx.x;
    int stride = gridDim.x * blockDim.x;
    for (; i < EE; i += stride) {
        long long dst = load_idx(ei, (long long)EE + i, is64);
        atomicAdd(&g_cnt[dst], 1.0f);
    }
}

// ---------------- composed edge weights (parallel) ----------------
__global__ void wcomb_kernel(const float* __restrict__ edge_W,
                             const float* __restrict__ edge_b,
                             const float* __restrict__ emW1,
                             const float* __restrict__ emb1) {
    __shared__ float sW1[HH * HH];
    __shared__ float sEW[EDGE_C * HH];
    int l = blockIdx.x;
    int tid = threadIdx.x; // 1024
    const float* W1l = emW1 + l * (2 * HH * HH) + HH * HH; // lower rows (64..127)
    for (int i = tid; i < HH * HH; i += 1024) sW1[i] = W1l[i];
    if (tid < EDGE_C * HH) sEW[tid] = edge_W[tid];
    __syncthreads();
    int k = tid >> 6, j = tid & 63;
    float acc = 0.f;
#pragma unroll 16
    for (int t = 0; t < HH; t++) acc += sEW[k * HH + t] * sW1[t * HH + j];
    g_Wcomb[l * EDGE_C * HH + k * HH + j] = acc;
    if (k == 0) {
        float accb = emb1[l * HH + j];
        for (int t = 0; t < HH; t++) accb += edge_b[t] * sW1[t * HH + j];
        g_bcomb[l * HH + j] = accb;
    }
}

// ---------------- composed node-update weights ----------------
// V1[l] = [umW1_top ; emW2@umW1_bot], bae = emb2@umW1_bot
// Whp[l] = umW2@emW1[l+1]_top, bhp = umb2@emW1[l+1]_top
__global__ void compose_kernel(const float* __restrict__ umW1,
                               const float* __restrict__ emW2,
                               const float* __restrict__ emb2,
                               const float* __restrict__ umW2,
                               const float* __restrict__ umb2,
                               const float* __restrict__ emW1) {
    __shared__ float sA[HH * HH];
    __shared__ float sB[HH * HH];
    int l = blockIdx.x;
    int tid = threadIdx.x; // 1024
    for (int i = tid; i < 4096; i += 1024) {
        g_V1[l * 8192 + i] = umW1[l * 8192 + i];          // top copy
        sA[i] = emW2[l * 4096 + i];
        sB[i] = umW1[l * 8192 + 4096 + i];                // bottom rows
    }
    __syncthreads();
    for (int o = tid; o < 4096; o += 1024) {
        int r = o >> 6, c = o & 63;
        float s = 0.f;
#pragma unroll 16
        for (int t = 0; t < HH; t++) s += sA[r * 64 + t] * sB[t * 64 + c];
        g_V1[l * 8192 + 4096 + o] = s;
    }
    if (tid < 64) {
        float s = 0.f;
        for (int t = 0; t < HH; t++) s += emb2[l * 64 + t] * sB[t * 64 + tid];
        g_bae[l * 64 + tid] = s;
    }
    if (l + 1 < LL) {
        __syncthreads();
        for (int i = tid; i < 4096; i += 1024) {
            sA[i] = umW2[l * 4096 + i];
            sB[i] = emW1[(l + 1) * 8192 + i];             // next layer top rows
        }
        __syncthreads();
        for (int o = tid; o < 4096; o += 1024) {
            int r = o >> 6, c = o & 63;
            float s = 0.f;
#pragma unroll 16
            for (int t = 0; t < HH; t++) s += sA[r * 64 + t] * sB[t * 64 + c];
            g_Whp[l * 4096 + o] = s;
        }
        if (tid < 64) {
            float s = 0.f;
            for (int t = 0; t < HH; t++) s += umb2[l * 64 + t] * sB[t * 64 + tid];
            g_bhp[l * 64 + tid] = s;
        }
    }
}

// ---------------- node init: h = x@node_W + b ; hp = h @ emW1[0][0:64] ----------------
__global__ void init_node_kernel(const float* __restrict__ x,
                                 const float* __restrict__ nW,
                                 const float* __restrict__ nb,
                                 const float* __restrict__ emW1) {
    __shared__ float sW[IN_C * HH];
    __shared__ float sP[HH * HH];
    __shared__ float sb[HH];
    __shared__ float sx[4][IN_C];
    __shared__ float sh[4][HH];
    int tid = threadIdx.x; // 256
    for (int i = tid; i < IN_C * HH; i += 256) sW[i] = nW[i];
    for (int i = tid; i < HH * HH; i += 256) sP[i] = emW1[i]; // layer0 upper rows
    if (tid < HH) sb[tid] = nb[tid];
    int tx = tid & 63, ty = tid >> 6;
    int node = blockIdx.x * 4 + ty;
    __syncthreads();
    if (node < NN && tx < IN_C) sx[ty][tx] = x[node * IN_C + tx];
    __syncthreads();
    float h = 0.f;
    if (node < NN) {
        h = sb[tx];
#pragma unroll
        for (int k = 0; k < IN_C; k++) h += sx[ty][k] * sW[k * HH + tx];
        g_h[node * HH + tx] = h;
        sh[ty][tx] = h;
    }
    __syncthreads();
    if (node < NN) {
        float hp = 0.f;
#pragma unroll 16
        for (int k = 0; k < HH; k++) hp += sh[ty][k] * sP[k * HH + tx];
        g_hp[node * HH + tx] = hp;
    }
}

// ---------------- edge kernel (R1 version: 16-thread groups + RED.v4) ----------------
__global__ void edge_kernel(const void* __restrict__ ei,
                            const float* __restrict__ edge_attr, int l) {
    __shared__ float sW[EDGE_C * HH];
    __shared__ float sb[HH];
    int tid = threadIdx.x;
    for (int i = tid; i < EDGE_C * HH; i += blockDim.x) sW[i] = g_Wcomb[l * EDGE_C * HH + i];
    if (tid < HH) sb[tid] = g_bcomb[l * HH + tid];
    __syncthreads();
    const int is64 = g_ei64;
    const int lane = tid & 31;
    const int q = tid & 15;
    const int base16 = lane & 16;
    const unsigned gmask = 0xFFFFu << base16;
    const long long* p64 = (const long long*)ei;
    const int* p32 = (const int*)ei;
    int e = blockIdx.x * (blockDim.x >> 4) + (tid >> 4);
    const int estride = gridDim.x * (blockDim.x >> 4);
    for (; e < EE; e += estride) {
        long long s64 = 0, d64 = 0;
        if (q == 0) {
            s64 = is64 ? p64[e] : (long long)p32[e];
            d64 = is64 ? p64[(long long)EE + e] : (long long)p32[EE + e];
        }
        s64 = __shfl_sync(gmask, s64, base16);
        d64 = __shfl_sync(gmask, d64, base16);
        int src = (int)s64, dst = (int)d64;
        float ea = edge_attr[(long long)e * EDGE_C + q];
        float4 acc = *(const float4*)(g_hp + (long long)src * HH + q * 4);
        float4 bb = *(const float4*)(sb + q * 4);
        acc.x += bb.x; acc.y += bb.y; acc.z += bb.z; acc.w += bb.w;
#pragma unroll
        for (int k = 0; k < EDGE_C; k++) {
            float a = __shfl_sync(gmask, ea, base16 + k);
            float4 w = *(const float4*)(sW + k * HH + q * 4);
            acc.x += a * w.x; acc.y += a * w.y; acc.z += a * w.z; acc.w += a * w.w;
        }
        acc.x = fmaxf(acc.x, 0.f); acc.y = fmaxf(acc.y, 0.f);
        acc.z = fmaxf(acc.z, 0.f); acc.w = fmaxf(acc.w, 0.f);
        float* dp = g_agg + (long long)dst * HH + q * 4;
        asm volatile("red.global.add.v4.f32 [%0], {%1,%2,%3,%4};"
                     :: "l"(dp), "f"(acc.x), "f"(acc.y), "f"(acc.z), "f"(acc.w)
                     : "memory");
    }
}

// ---------------- fused node update, f32x2 register-blocked ----------------
// t = relu([h|aggH]@V1 + cnt*bae + umb1); h' = t@umW2 + umb2; hp' = t@Whp + bhp
// 256 threads = 8 warps; warp handles 8 nodes, lane owns channel pair {2l,2l+1}.
#define NU2_SMEM_FLOATS (8192 + 4096 + 4096 + 8192 + 4096 + 256)
__global__ __launch_bounds__(256) void node_update2(const float* __restrict__ umb1,
                                                    const float* __restrict__ umW2,
                                                    const float* __restrict__ umb2,
                                                    int l, int has_next) {
    extern __shared__ float sm[];
    float* sV1 = sm;                 // [128][64]
    float* sW2 = sV1 + 8192;         // [64][64]
    float* sWhp = sW2 + 4096;        // [64][64]
    float* sIn = sWhp + 4096;        // [64][128]
    float* sT = sIn + 8192;          // [64][64]
    float* sB = sT + 4096;           // umb1 | bae | umb2 | bhp
    int tid = threadIdx.x;
    for (int i = tid; i < 8192; i += 256) sV1[i] = g_V1[l * 8192 + i];
    for (int i = tid; i < 4096; i += 256) sW2[i] = umW2[l * 4096 + i];
    if (has_next)
        for (int i = tid; i < 4096; i += 256) sWhp[i] = g_Whp[l * 4096 + i];
    if (tid < 64) {
        sB[tid] = umb1[l * 64 + tid];
        sB[64 + tid] = g_bae[l * 64 + tid];
        sB[128 + tid] = umb2[l * 64 + tid];
        sB[192 + tid] = has_next ? g_bhp[l * 64 + tid] : 0.f;
    }
    __syncthreads();
    const int w = tid >> 5, lane = tid & 31;
    const int nb = w * 8;
    const ull b12 = *(const ull*)&sB[2 * lane];
    const ull bae2 = *(const ull*)&sB[64 + 2 * lane];
    const ull b22 = *(const ull*)&sB[128 + 2 * lane];
    const ull bh2 = *(const ull*)&sB[192 + 2 * lane];

    for (int base = blockIdx.x * 64; base < NN; base += gridDim.x * 64) {
        // cooperative stage-in: sIn[n][0:64]=h, [64:128]=aggH
        for (int i = tid; i < 2048; i += 256) {
            int n = i >> 5, qq = i & 31;
            int node = base + n;
            float4 v = make_float4(0.f, 0.f, 0.f, 0.f);
            if (node < NN) {
                v = (qq < 16) ? *(const float4*)(g_h + (long long)node * 64 + qq * 4)
                              : *(const float4*)(g_agg + (long long)node * 64 + (qq - 16) * 4);
            }
            ((float4*)sIn)[n * 32 + qq] = v;
        }
        __syncthreads();
        // ---- S1: t = relu(u @ V1 + cnt*bae + umb1)
        ull acc[8];
#pragma unroll
        for (int b = 0; b < 8; b++) {
            int node = base + nb + b;
            float cn = (node < NN) ? g_cnt[node] : 0.f;
            acc[b] = fma2(pack2(cn, cn), bae2, b12);
        }
#pragma unroll 4
        for (int kq = 0; kq < 32; kq++) {
            const float* wr = &sV1[kq * 256 + 2 * lane];
            ull w0 = *(const ull*)(wr);
            ull w1 = *(const ull*)(wr + 64);
            ull w2 = *(const ull*)(wr + 128);
            ull w3 = *(const ull*)(wr + 192);
#pragma unroll
            for (int b = 0; b < 8; b++) {
                float4 a = *(const float4*)&sIn[(nb + b) * 128 + kq * 4];
                acc[b] = fma2(pack2(a.x, a.x), w0, acc[b]);
                acc[b] = fma2(pack2(a.y, a.y), w1, acc[b]);
                acc[b] = fma2(pack2(a.z, a.z), w2, acc[b]);
                acc[b] = fma2(pack2(a.w, a.w), w3, acc[b]);
            }
        }
#pragma unroll
        for (int b = 0; b < 8; b++) {
            float lo, hi;
            unpack2(acc[b], lo, hi);
            *(ull*)&sT[(nb + b) * 64 + 2 * lane] = pack2(fmaxf(lo, 0.f), fmaxf(hi, 0.f));
        }
        __syncwarp();
        // ---- S2(+S3): h' = t@umW2 + umb2 ; hp' = t@Whp + bhp
        ull a2[8], a3[8];
#pragma unroll
        for (int b = 0; b < 8; b++) { a2[b] = b22; a3[b] = bh2; }
        if (has_next) {
#pragma unroll 2
            for (int kq = 0; kq < 16; kq++) {
                const float* w2r = &sW2[kq * 256 + 2 * lane];
                const float* whr = &sWhp[kq * 256 + 2 * lane];
                ull p0 = *(const ull*)(w2r), p1 = *(const ull*)(w2r + 64);
                ull p2 = *(const ull*)(w2r + 128), p3 = *(const ull*)(w2r + 192);
                ull q0 = *(const ull*)(whr), q1 = *(const ull*)(whr + 64);
                ull q2 = *(const ull*)(whr + 128), q3 = *(const ull*)(whr + 192);
#pragma unroll
                for (int b = 0; b < 8; b++) {
                    float4 a = *(const float4*)&sT[(nb + b) * 64 + kq * 4];
                    ull d;
                    d = pack2(a.x, a.x); a2[b] = fma2(d, p0, a2[b]); a3[b] = fma2(d, q0, a3[b]);
                    d = pack2(a.y, a.y); a2[b] = fma2(d, p1, a2[b]); a3[b] = fma2(d, q1, a3[b]);
                    d = pack2(a.z, a.z); a2[b] = fma2(d, p2, a2[b]); a3[b] = fma2(d, q2, a3[b]);
                    d = pack2(a.w, a.w); a2[b] = fma2(d, p3, a2[b]); a3[b] = fma2(d, q3, a3[b]);
                }
            }
#pragma unroll
            for (int b = 0; b < 8; b++) {
                int node = base + nb + b;
                if (node < NN) {
                    *(ull*)&g_h[(long long)node * 64 + 2 * lane] = a2[b];
                    *(ull*)&g_hp[(long long)node * 64 + 2 * lane] = a3[b];
                }
            }
        } else {
#pragma unroll 2
            for (int kq = 0; kq < 16; kq++) {
                const float* w2r = &sW2[kq * 256 + 2 * lane];
                ull p0 = *(const ull*)(w2r), p1 = *(const ull*)(w2r + 64);
                ull p2 = *(const ull*)(w2r + 128), p3 = *(const ull*)(w2r + 192);
#pragma unroll
                for (int b = 0; b < 8; b++) {
                    float4 a = *(const float4*)&sT[(nb + b) * 64 + kq * 4];
                    a2[b] = fma2(pack2(a.x, a.x), p0, a2[b]);
                    a2[b] = fma2(pack2(a.y, a.y), p1, a2[b]);
                    a2[b] = fma2(pack2(a.z, a.z), p2, a2[b]);
                    a2[b] = fma2(pack2(a.w, a.w), p3, a2[b]);
                }
            }
#pragma unroll
            for (int b = 0; b < 8; b++) {
                int node = base + nb + b;
                if (node < NN)
                    *(ull*)&g_h[(long long)node * 64 + 2 * lane] = a2[b];
            }
        }
        __syncthreads();
    }
}

// ---------------- global mean pool ----------------
__global__ void pool_kernel(const void* __restrict__ batch) {
    int is64 = g_b64;
    long long i = (long long)blockIdx.x * blockDim.x + threadIdx.x;
    if (i >= (long long)NN * 64) return;
    long long node = i >> 6; int ch = (int)(i & 63);
    long long b = load_idx(batch, node, is64);
    atomicAdd(&g_pool[b * 64 + ch], g_h[i]);
    if (ch == 0) atomicAdd(&g_pcnt[b], 1.0f);
}

// ---------------- readout ----------------
__global__ void readout_kernel(const float* __restrict__ desc,
                               const float* __restrict__ W1, const float* __restrict__ b1,
                               const float* __restrict__ W2, const float* __restrict__ b2,
                               float* __restrict__ out) {
    __shared__ float r[HH + DESCC];
    __shared__ float st[128];
    int g = blockIdx.x, tid = threadIdx.x; // 128 threads
    float cn = fmaxf(g_pcnt[g], 1.0f);
    for (int i = tid; i < HH; i += 128) r[i] = g_pool[g * HH + i] / cn;
    for (int i = tid; i < DESCC; i += 128) r[HH + i] = desc[(long long)g * DESCC + i];
    __syncthreads();
    float acc = b1[tid];
#pragma unroll 8
    for (int k = 0; k < HH + DESCC; k++) acc += r[k] * W1[k * 128 + tid];
    acc = fmaxf(acc, 0.f);
    st[tid] = acc * W2[tid];
    __syncthreads();
    for (int s = 64; s > 0; s >>= 1) {
        if (tid < s) st[tid] += st[tid + s];
        __syncthreads();
    }
    if (tid == 0) out[g] = 1.0f / (1.0f + expf(-(st[0] + b2[0])));
}

// ---------------- launch ----------------
extern "C" void kernel_launch(void* const* d_in, const int* in_sizes, int n_in,
                              void* d_out, int out_size) {
    const float* x       = (const float*)d_in[0];
    const void*  ei      = d_in[1];
    const float* eattr   = (const float*)d_in[2];
    const void*  batch   = d_in[3];
    const float* desc    = (const float*)d_in[4];
    const float* node_W  = (const float*)d_in[5];
    const float* node_b  = (const float*)d_in[6];
    const float* edge_W  = (const float*)d_in[7];
    const float* edge_b  = (const float*)d_in[8];
    const float* emW1    = (const float*)d_in[9];
    const float* emb1    = (const float*)d_in[10];
    const float* emW2    = (const float*)d_in[11];
    const float* emb2    = (const float*)d_in[12];
    const float* umW1    = (const float*)d_in[13];
    const float* umb1    = (const float*)d_in[14];
    const float* umW2    = (const float*)d_in[15];
    const float* umb2    = (const float*)d_in[16];
    const float* roW1    = (const float*)d_in[17];
    const float* rob1    = (const float*)d_in[18];
    const float* roW2    = (const float*)d_in[19];
    const float* rob2    = (const float*)d_in[20];
    float* out = (float*)d_out;

    const int nu_smem = NU2_SMEM_FLOATS * (int)sizeof(float);
    cudaFuncSetAttribute(node_update2,
                         cudaFuncAttributeMaxDynamicSharedMemorySize, nu_smem);

    detect_kernel<<<1, 32>>>(ei, batch);
    zero_misc_kernel<<<512, 256>>>();
    count_kernel<<<2048, 256>>>(ei);
    wcomb_kernel<<<LL, 1024>>>(edge_W, edge_b, emW1, emb1);
    compose_kernel<<<LL, 1024>>>(umW1, emW2, emb2, umW2, umb2, emW1);
    init_node_kernel<<<(NN + 3) / 4, 256>>>(x, node_W, node_b, emW1);
    for (int l = 0; l < LL; l++) {
        zero_agg_kernel<<<2048, 256>>>();
        edge_kernel<<<4096, 256>>>(ei, eattr, l);
        node_update2<<<148, 256, nu_smem>>>(umb1, umW2, umb2, l, l < LL - 1 ? 1 : 0);
    }
    pool_kernel<<<(NN * 64 + 255) / 256, 256>>>(batch);
    readout_kernel<<<GG, 128>>>(desc, roW1, rob1, roW2, rob2, out);
}